// round 9
// baseline (speedup 1.0000x reference)
#include <cuda_runtime.h>

#define N3 9604
#define N4 2401
#define N5 625
#define NA 37890            // (N3+N4+N5)*3
#define NGT 64
#define LANES 8             // threads cooperating per anchor
#define SCALE_CLAMP 3.3322045101752038f   // log(224/8), double-rounded
#define NEGBIG 1.0e8f

// Anchor (w,h) per [level*3 + aspect_ratio_index], computed in double on host:
// area = (4*stride)^2; w = sqrt(area/ar); h = area/w;  ar in {0.5, 1.0, 2.0}
__constant__ float c_w[9] = {
    45.254833995939045f,  32.0f,  22.627416997969522f,   // p3 (stride 8)
    90.50966799187809f,   64.0f,  45.254833995939045f,   // p4 (stride 16)
    181.01933598375618f, 128.0f,  90.50966799187809f     // p5 (stride 32)
};
__constant__ float c_h[9] = {
    22.627416997969522f,  32.0f,  45.254833995939045f,
    45.254833995939045f,  64.0f,  90.50966799187809f,
    90.50966799187809f,  128.0f, 181.01933598375618f
};

__global__ __launch_bounds__(256)
void rpn_fused_kernel(const float* __restrict__ deltas,
                      const float* __restrict__ gt,
                      float* __restrict__ out)
{
    __shared__ float4 s_box[NGT];   // gt box coords
    __shared__ float  s_area[NGT];  // gt areas
    __shared__ float  s_cls[NGT];   // gt class

    const int tid = threadIdx.x;
    if (tid < NGT) {
        const float g0 = gt[tid * 5 + 0];
        const float g1 = gt[tid * 5 + 1];
        const float g2 = gt[tid * 5 + 2];
        const float g3 = gt[tid * 5 + 3];
        s_box[tid]  = make_float4(g0, g1, g2, g3);
        s_cls[tid]  = gt[tid * 5 + 4];
        s_area[tid] = (g2 - g0) * (g3 - g1);
    }
    __syncthreads();

    const int gid   = blockIdx.x * blockDim.x + tid;
    const int a_raw = gid >> 3;          // anchor id
    const int sub   = gid & 7;           // lane within group of 8
    const bool valid = (a_raw < NA);
    const int a = valid ? a_raw : 0;     // clamp: no thread exits before shfl

    // ---- decode level / grid coords ARITHMETICALLY (no loc LDG needed).
    // Reference locations are ((i+0.5)*stride) in f32: (i+0.5) is exact in
    // f32 and stride is a power of two, so this is bit-identical. ----
    unsigned li, locidx, ar, col, row;
    float stride;
    {
        unsigned r;
        if (a < 3 * N3) {
            li = 0; r = (unsigned)a;
            locidx = r / 3u; ar = r - locidx * 3u;
            col = locidx % 98u; row = locidx / 98u;
            stride = 8.0f;
        } else if (a < 3 * (N3 + N4)) {
            li = 1; r = (unsigned)(a - 3 * N3);
            locidx = r / 3u; ar = r - locidx * 3u;
            col = locidx % 49u; row = locidx / 49u;
            stride = 16.0f;
        } else {
            li = 2; r = (unsigned)(a - 3 * (N3 + N4));
            locidx = r / 3u; ar = r - locidx * 3u;
            col = locidx % 25u; row = locidx / 25u;
            stride = 32.0f;
        }
    }
    const float xc = ((float)col + 0.5f) * stride;   // exact, matches reference
    const float yc = ((float)row + 0.5f) * stride;
    const float w  = c_w[li * 3 + ar];
    const float h  = c_h[li * 3 + ar];

    // anchor box (matches reference rounding: xc - w/2 etc., all f32)
    const float ax0 = xc - 0.5f * w;
    const float ay0 = yc - 0.5f * h;
    const float ax1 = xc + 0.5f * w;
    const float ay1 = yc + 0.5f * h;

    // recompute wa/ha from the box like the reference does (f32 rounding parity)
    const float wa = ax1 - ax0;
    const float ha = ay1 - ay0;
    const float xa = ax0 + wa * 0.5f;
    const float ya = ay0 + ha * 0.5f;

    // ---- lane 1: apply deltas -> proposals (independent; overlaps IoU loop) ----
    if (sub == 1 && valid) {
        const float4 d  = reinterpret_cast<const float4*>(deltas)[a];
        const float dw  = fminf(d.z, SCALE_CLAMP);
        const float dh  = fminf(d.w, SCALE_CLAMP);
        const float xp  = d.x * wa + xa;
        const float yp  = d.y * ha + ya;
        const float wp  = expf(dw) * wa;
        const float hp  = expf(dh) * ha;
        float4 prop;
        prop.x = xp - 0.5f * wp;
        prop.y = yp - 0.5f * hp;
        prop.z = xp + 0.5f * wp;
        prop.w = yp + 0.5f * hp;
        reinterpret_cast<float4*>(out)[a] = prop;  // out base 16B-aligned
    }

    // ---- IoU argmax over this lane's strided subset of GT boxes.
    //
    // best/bidx init to 0: jnp.argmax over all-zero IoUs returns index 0 with
    // quality 0, which is exactly (best=0, bidx=0). The lazy-division filter
    // (inter > bestm*uni; bestm=0 initially) therefore skips EVERY
    // zero-intersection GT with no division at all — ~99% of pairs.
    //
    // Lazy division is exact: RN monotone + best representable =>
    // RN(inter/uni) > best requires inter > best*uni; bestm = best*(1-2^-21)
    // absorbs both f32 roundings, so the filter over-triggers but never skips
    // a true winner; best itself is always an exact rounded quotient.
    //
    // TWO independent accumulator chains (A: g<32, B: g>=32) halve the
    // loop-carried latency; exact merge (A's indices all smaller, so
    // tie -> keep A preserves first-occurrence argmax). Loads are hoisted one
    // iteration ahead to cover LDS latency with compare math. ----
    const float aarea = wa * ha;
    float bestA = 0.0f, bmA = 0.0f;  int idxA = 0;
    float bestB = 0.0f, bmB = 0.0f;  int idxB = 0;

    float4 boxA = s_box[sub];
    float  arA  = s_area[sub];
    float4 boxB = s_box[sub + 32];
    float  arB  = s_area[sub + 32];

    #pragma unroll
    for (int i = 0; i < 4; ++i) {
        const float4 cA = boxA; const float aA = arA;
        const float4 cB = boxB; const float aB = arB;
        if (i < 3) {                     // prefetch next pair
            boxA = s_box[sub + ((i + 1) << 3)];
            arA  = s_area[sub + ((i + 1) << 3)];
            boxB = s_box[sub + 32 + ((i + 1) << 3)];
            arB  = s_area[sub + 32 + ((i + 1) << 3)];
        }
        {
            const int g = sub + (i << 3);
            float iw = fminf(ax1, cA.z) - fmaxf(ax0, cA.x);
            float ih = fminf(ay1, cA.w) - fmaxf(ay0, cA.y);
            iw = fmaxf(iw, 0.0f);
            ih = fmaxf(ih, 0.0f);
            const float inter = iw * ih;
            const float uni   = aarea + aA - inter;
            if (inter > bmA * uni) {
                const float q = inter / uni;     // exact rounded quotient (rare)
                if (q > bestA) { bestA = q; idxA = g; bmA = bestA * 0.99999952f; }
            }
        }
        {
            const int g = sub + 32 + (i << 3);
            float iw = fminf(ax1, cB.z) - fmaxf(ax0, cB.x);
            float ih = fminf(ay1, cB.w) - fmaxf(ay0, cB.y);
            iw = fmaxf(iw, 0.0f);
            ih = fmaxf(ih, 0.0f);
            const float inter = iw * ih;
            const float uni   = aarea + aB - inter;
            if (inter > bmB * uni) {
                const float q = inter / uni;
                if (q > bestB) { bestB = q; idxB = g; bmB = bestB * 0.99999952f; }
            }
        }
    }
    float best = bestA;  int bidx = idxA;
    if (bestB > best) { best = bestB; bidx = idxB; }   // tie -> A (smaller g)

    // ---- 8-lane argmax reduction (first-occurrence ties -> smaller g) ----
    #pragma unroll
    for (int off = 1; off < LANES; off <<= 1) {
        const float ob = __shfl_xor_sync(0xffffffffu, best, off);
        const int   oi = __shfl_xor_sync(0xffffffffu, bidx, off);
        if (ob > best || (ob == best && oi < bidx)) { best = ob; bidx = oi; }
    }

    // ---- matched_gt (all lanes compute; lanes 0..4 each store one element) ----
    float m0, m1, m2, m3, m4;
    if (best <= 0.3f) {
        m0 = m1 = m2 = m3 = m4 = -1.0f;
    } else if (best < 0.6f) {
        m0 = m1 = m2 = m3 = m4 = -NEGBIG;
    } else {
        const float4 mb = s_box[bidx];
        m0 = mb.x; m1 = mb.y; m2 = mb.z; m3 = mb.w;
        m4 = s_cls[bidx];
    }

    if (valid) {
        float* om = out + (size_t)NA * 4 + (size_t)a * 5;
        if (sub == 0) om[0] = m0;
        else if (sub == 1) om[1] = m1;
        else if (sub == 2) om[2] = m2;
        else if (sub == 3) om[3] = m3;
        else if (sub == 4) om[4] = m4;
    }

    // ---- gt_deltas (lanes 5,6 store) ----
    if (valid && (sub == 5 || sub == 6)) {
        float gd0, gd1, gd2, gd3;
        if (m0 < 0.0f) {
            gd0 = gd1 = gd2 = gd3 = -NEGBIG;
        } else {
            const float wg = fmaxf(m2 - m0, 1.0f);
            const float hg = fmaxf(m3 - m1, 1.0f);
            const float xg = m0 + wg * 0.5f;
            const float yg = m1 + hg * 0.5f;
            gd0 = (xg - xa) / wa;
            gd1 = (yg - ya) / ha;
            gd2 = logf(wg / wa);
            gd3 = logf(hg / ha);
        }
        // gt_deltas section starts at element NA*9 = 341010 -> byte offset
        // ≡ 8 (mod 16): only 8B-aligned, so float2 stores.
        float* og = out + (size_t)NA * 9 + (size_t)a * 4;
        if (sub == 5) reinterpret_cast<float2*>(og)[0] = make_float2(gd0, gd1);
        else          reinterpret_cast<float2*>(og)[1] = make_float2(gd2, gd3);
    }
}

extern "C" void kernel_launch(void* const* d_in, const int* in_sizes, int n_in,
                              void* d_out, int out_size)
{
    const float* deltas = (const float*)d_in[3];
    const float* gt     = (const float*)d_in[4];
    float* out = (float*)d_out;

    const int threads = 256;
    const int blocks  = (NA * LANES + threads - 1) / threads;  // 1185
    rpn_fused_kernel<<<blocks, threads>>>(deltas, gt, out);
}

// round 10
// speedup vs baseline: 1.0208x; 1.0208x over previous
#include <cuda_runtime.h>

#define N3 9604
#define N4 2401
#define N5 625
#define NA 37890            // (N3+N4+N5)*3
#define NGT 64
#define LANES 8             // threads cooperating per anchor
#define SCALE_CLAMP 3.3322045101752038f   // log(224/8), double-rounded
#define NEGBIG 1.0e8f

// Anchor (w,h) per [level*3 + aspect_ratio_index], computed in double on host:
// area = (4*stride)^2; w = sqrt(area/ar); h = area/w;  ar in {0.5, 1.0, 2.0}
__constant__ float c_w[9] = {
    45.254833995939045f,  32.0f,  22.627416997969522f,   // p3 (stride 8)
    90.50966799187809f,   64.0f,  45.254833995939045f,   // p4 (stride 16)
    181.01933598375618f, 128.0f,  90.50966799187809f     // p5 (stride 32)
};
__constant__ float c_h[9] = {
    22.627416997969522f,  32.0f,  45.254833995939045f,
    45.254833995939045f,  64.0f,  90.50966799187809f,
    90.50966799187809f,  128.0f, 181.01933598375618f
};

__global__ __launch_bounds__(256)
void rpn_fused_kernel(const float* __restrict__ loc3,
                      const float* __restrict__ loc4,
                      const float* __restrict__ loc5,
                      const float* __restrict__ deltas,
                      const float* __restrict__ gt,
                      float* __restrict__ out)
{
    __shared__ float4 s_box[NGT];   // gt box coords
    __shared__ float  s_area[NGT];  // gt areas
    __shared__ float  s_cls[NGT];   // gt class

    const int tid = threadIdx.x;
    if (tid < NGT) {
        const float g0 = gt[tid * 5 + 0];
        const float g1 = gt[tid * 5 + 1];
        const float g2 = gt[tid * 5 + 2];
        const float g3 = gt[tid * 5 + 3];
        s_box[tid]  = make_float4(g0, g1, g2, g3);
        s_cls[tid]  = gt[tid * 5 + 4];
        s_area[tid] = (g2 - g0) * (g3 - g1);
    }
    __syncthreads();

    const int gid   = blockIdx.x * blockDim.x + tid;
    const int a_raw = gid >> 3;          // anchor id
    const int sub   = gid & 7;           // lane within group of 8
    const bool valid = (a_raw < NA);
    const int a = valid ? a_raw : 0;     // clamp: no thread exits before shfl

    // ---- which level / location / aspect ratio ----
    int li, r = a;
    const float* loc;
    if (a < 3 * N3)             { li = 0; loc = loc3; }
    else if (a < 3 * (N3 + N4)) { li = 1; loc = loc4; r = a - 3 * N3; }
    else                        { li = 2; loc = loc5; r = a - 3 * (N3 + N4); }
    const int locidx = r / 3;
    const int ar     = r - locidx * 3;

    const float xc = __ldg(&loc[2 * locidx + 0]);
    const float yc = __ldg(&loc[2 * locidx + 1]);
    const float w  = c_w[li * 3 + ar];
    const float h  = c_h[li * 3 + ar];

    // anchor box (matches reference rounding: xc - w/2 etc., all f32)
    const float ax0 = xc - 0.5f * w;
    const float ay0 = yc - 0.5f * h;
    const float ax1 = xc + 0.5f * w;
    const float ay1 = yc + 0.5f * h;

    // recompute wa/ha from the box like the reference does (f32 rounding parity)
    const float wa = ax1 - ax0;
    const float ha = ay1 - ay0;
    const float xa = ax0 + wa * 0.5f;
    const float ya = ay0 + ha * 0.5f;

    // ---- lane 1: apply deltas -> proposals (independent; overlaps IoU loop) ----
    if (sub == 1 && valid) {
        const float4 d  = reinterpret_cast<const float4*>(deltas)[a];
        const float dw  = fminf(d.z, SCALE_CLAMP);
        const float dh  = fminf(d.w, SCALE_CLAMP);
        const float xp  = d.x * wa + xa;
        const float yp  = d.y * ha + ya;
        const float wp  = expf(dw) * wa;
        const float hp  = expf(dh) * ha;
        float4 prop;
        prop.x = xp - 0.5f * wp;
        prop.y = yp - 0.5f * hp;
        prop.z = xp + 0.5f * wp;
        prop.w = yp + 0.5f * hp;
        reinterpret_cast<float4*>(out)[a] = prop;  // out base 16B-aligned
    }

    // ---- IoU argmax over this lane's strided subset of GT boxes.
    //
    // best/bidx init to 0: jnp.argmax over an all-zero IoU row returns
    // (index 0, quality 0) == (bidx=0, best=0) exactly. With bestm=0 the
    // lazy filter (inter > bestm*uni) skips every zero-intersection GT with
    // NO division — the overwhelming majority of pairs.
    //
    // Lazy division is exact: RN is monotone and best is representable, so
    // RN(inter/uni) > best requires inter > best*uni. bestm = best*(1-2^-21)
    // absorbs both f32 roundings: the filter may over-trigger, never skips a
    // true winner; best is always an exact rounded quotient, so strict-> +
    // in-order g preserves first-occurrence argmax ties. ----
    const float aarea = wa * ha;
    float best  = 0.0f;
    float bestm = 0.0f;
    int   bidx  = 0;
    #pragma unroll
    for (int i = 0; i < NGT / LANES; ++i) {
        const int g = sub + (i << 3);
        const float4 gb = s_box[g];
        float iw = fminf(ax1, gb.z) - fmaxf(ax0, gb.x);
        float ih = fminf(ay1, gb.w) - fmaxf(ay0, gb.y);
        iw = fmaxf(iw, 0.0f);
        ih = fmaxf(ih, 0.0f);
        const float inter = iw * ih;
        const float uni   = aarea + s_area[g] - inter;
        if (inter > bestm * uni) {
            const float q = inter / uni;     // exact rounded quotient (rare)
            if (q > best) { best = q; bidx = g; bestm = best * 0.99999952f; }
        }
    }

    // ---- 8-lane argmax reduction (first-occurrence ties -> smaller g) ----
    #pragma unroll
    for (int off = 1; off < LANES; off <<= 1) {
        const float ob = __shfl_xor_sync(0xffffffffu, best, off);
        const int   oi = __shfl_xor_sync(0xffffffffu, bidx, off);
        if (ob > best || (ob == best && oi < bidx)) { best = ob; bidx = oi; }
    }

    // ---- matched_gt (all lanes compute; lanes 0..4 each store one element) ----
    float m0, m1, m2, m3, m4;
    if (best <= 0.3f) {
        m0 = m1 = m2 = m3 = m4 = -1.0f;
    } else if (best < 0.6f) {
        m0 = m1 = m2 = m3 = m4 = -NEGBIG;
    } else {
        const float4 mb = s_box[bidx];
        m0 = mb.x; m1 = mb.y; m2 = mb.z; m3 = mb.w;
        m4 = s_cls[bidx];
    }

    if (valid) {
        float* om = out + (size_t)NA * 4 + (size_t)a * 5;
        if (sub == 0) om[0] = m0;
        else if (sub == 1) om[1] = m1;
        else if (sub == 2) om[2] = m2;
        else if (sub == 3) om[3] = m3;
        else if (sub == 4) om[4] = m4;
    }

    // ---- gt_deltas (lanes 5,6 store) ----
    if (valid && (sub == 5 || sub == 6)) {
        float gd0, gd1, gd2, gd3;
        if (m0 < 0.0f) {
            gd0 = gd1 = gd2 = gd3 = -NEGBIG;
        } else {
            const float wg = fmaxf(m2 - m0, 1.0f);
            const float hg = fmaxf(m3 - m1, 1.0f);
            const float xg = m0 + wg * 0.5f;
            const float yg = m1 + hg * 0.5f;
            gd0 = (xg - xa) / wa;
            gd1 = (yg - ya) / ha;
            gd2 = logf(wg / wa);
            gd3 = logf(hg / ha);
        }
        // gt_deltas section starts at element NA*9 = 341010 -> byte offset
        // ≡ 8 (mod 16): only 8B-aligned, so float2 stores.
        float* og = out + (size_t)NA * 9 + (size_t)a * 4;
        if (sub == 5) reinterpret_cast<float2*>(og)[0] = make_float2(gd0, gd1);
        else          reinterpret_cast<float2*>(og)[1] = make_float2(gd2, gd3);
    }
}

extern "C" void kernel_launch(void* const* d_in, const int* in_sizes, int n_in,
                              void* d_out, int out_size)
{
    const float* loc3   = (const float*)d_in[0];
    const float* loc4   = (const float*)d_in[1];
    const float* loc5   = (const float*)d_in[2];
    const float* deltas = (const float*)d_in[3];
    const float* gt     = (const float*)d_in[4];
    float* out = (float*)d_out;

    const int threads = 256;
    const int blocks  = (NA * LANES + threads - 1) / threads;  // 1185
    rpn_fused_kernel<<<blocks, threads>>>(loc3, loc4, loc5, deltas, gt, out);
}

// round 12
// speedup vs baseline: 1.1283x; 1.1053x over previous
#include <cuda_runtime.h>

#define N3 9604
#define N4 2401
#define N5 625
#define NA 37890            // (N3+N4+N5)*3
#define NGT 64
#define LANES 4             // threads cooperating per anchor
#define SCALE_CLAMP 3.3322045101752038f   // log(224/8), double-rounded
#define NEGBIG 1.0e8f

// Anchor (w,h) per [level*3 + aspect_ratio_index], computed in double on host:
// area = (4*stride)^2; w = sqrt(area/ar); h = area/w;  ar in {0.5, 1.0, 2.0}
__constant__ float c_w[9] = {
    45.254833995939045f,  32.0f,  22.627416997969522f,   // p3 (stride 8)
    90.50966799187809f,   64.0f,  45.254833995939045f,   // p4 (stride 16)
    181.01933598375618f, 128.0f,  90.50966799187809f     // p5 (stride 32)
};
__constant__ float c_h[9] = {
    22.627416997969522f,  32.0f,  45.254833995939045f,
    45.254833995939045f,  64.0f,  90.50966799187809f,
    90.50966799187809f,  128.0f, 181.01933598375618f
};

__global__ __launch_bounds__(256)
void rpn_fused_kernel(const float* __restrict__ loc3,
                      const float* __restrict__ loc4,
                      const float* __restrict__ loc5,
                      const float* __restrict__ deltas,
                      const float* __restrict__ gt,
                      float* __restrict__ out)
{
    __shared__ float4 s_box[NGT];   // gt box coords
    __shared__ float  s_area[NGT];  // gt areas
    __shared__ float  s_cls[NGT];   // gt class

    const int tid = threadIdx.x;
    if (tid < NGT) {
        const float g0 = gt[tid * 5 + 0];
        const float g1 = gt[tid * 5 + 1];
        const float g2 = gt[tid * 5 + 2];
        const float g3 = gt[tid * 5 + 3];
        s_box[tid]  = make_float4(g0, g1, g2, g3);
        s_cls[tid]  = gt[tid * 5 + 4];
        s_area[tid] = (g2 - g0) * (g3 - g1);
    }
    __syncthreads();

    const int gid   = blockIdx.x * blockDim.x + tid;
    const int a_raw = gid >> 2;          // anchor id
    const int sub   = gid & 3;           // lane within group of 4
    const bool valid = (a_raw < NA);
    const int a = valid ? a_raw : 0;     // clamp: no thread exits before shfl

    // ---- which level / location / aspect ratio ----
    int li, r = a;
    const float* loc;
    if (a < 3 * N3)             { li = 0; loc = loc3; }
    else if (a < 3 * (N3 + N4)) { li = 1; loc = loc4; r = a - 3 * N3; }
    else                        { li = 2; loc = loc5; r = a - 3 * (N3 + N4); }
    const int locidx = r / 3;
    const int ar     = r - locidx * 3;

    const float xc = __ldg(&loc[2 * locidx + 0]);
    const float yc = __ldg(&loc[2 * locidx + 1]);
    const float w  = c_w[li * 3 + ar];
    const float h  = c_h[li * 3 + ar];

    // anchor box (matches reference rounding: xc - w/2 etc., all f32)
    const float ax0 = xc - 0.5f * w;
    const float ay0 = yc - 0.5f * h;
    const float ax1 = xc + 0.5f * w;
    const float ay1 = yc + 0.5f * h;

    // recompute wa/ha from the box like the reference does (f32 rounding parity)
    const float wa = ax1 - ax0;
    const float ha = ay1 - ay0;
    const float xa = ax0 + wa * 0.5f;
    const float ya = ay0 + ha * 0.5f;

    // ---- lane 0: apply deltas -> proposals (independent; overlaps IoU loop) ----
    if (sub == 0 && valid) {
        const float4 d  = reinterpret_cast<const float4*>(deltas)[a];
        const float dw  = fminf(d.z, SCALE_CLAMP);
        const float dh  = fminf(d.w, SCALE_CLAMP);
        const float xp  = d.x * wa + xa;
        const float yp  = d.y * ha + ya;
        const float wp  = expf(dw) * wa;
        const float hp  = expf(dh) * ha;
        float4 prop;
        prop.x = xp - 0.5f * wp;
        prop.y = yp - 0.5f * hp;
        prop.z = xp + 0.5f * wp;
        prop.w = yp + 0.5f * hp;
        reinterpret_cast<float4*>(out)[a] = prop;  // out base 16B-aligned
    }

    // ---- IoU argmax over this lane's strided subset (g ≡ sub mod 4).
    //
    // best/bidx init to 0: jnp.argmax over an all-zero IoU row returns
    // (index 0, quality 0) == (bidx=0, best=0) exactly. With bestm=0 the
    // lazy filter (inter > bestm*uni) skips every zero-intersection GT with
    // NO division — the overwhelming majority of pairs.
    //
    // Lazy division is exact: RN is monotone and best is representable, so
    // RN(inter/uni) > best requires inter > best*uni. bestm = best*(1-2^-21)
    // absorbs both f32 roundings: the filter may over-trigger, never skips a
    // true winner; best is always an exact rounded quotient, so strict-> +
    // increasing-g processing preserves first-occurrence argmax ties.
    //
    // Pairs of consecutive-in-order candidates (g, g+4) share ONE branch
    // region: the merged entry test uses region-entry bestm, which only
    // grows, so it is a superset of the exact per-candidate tests redone
    // inside. Halves branch-management overhead. ----
    const float aarea = wa * ha;
    float best  = 0.0f;
    float bestm = 0.0f;
    int   bidx  = 0;
    #pragma unroll
    for (int i = 0; i < 8; ++i) {
        const int g0 = sub + (i << 3);       // sub, sub+8, ... increasing
        const int g1 = g0 + 4;               // interleaved, still increasing
        const float4 b0 = s_box[g0];
        const float4 b1 = s_box[g1];
        const float a0 = s_area[g0];
        const float a1 = s_area[g1];

        float iw0 = fmaxf(fminf(ax1, b0.z) - fmaxf(ax0, b0.x), 0.0f);
        float ih0 = fmaxf(fminf(ay1, b0.w) - fmaxf(ay0, b0.y), 0.0f);
        float iw1 = fmaxf(fminf(ax1, b1.z) - fmaxf(ax0, b1.x), 0.0f);
        float ih1 = fmaxf(fminf(ay1, b1.w) - fmaxf(ay0, b1.y), 0.0f);
        const float in0 = iw0 * ih0;
        const float in1 = iw1 * ih1;
        const float un0 = aarea + a0 - in0;
        const float un1 = aarea + a1 - in1;

        if ((in0 > bestm * un0) | (in1 > bestm * un1)) {
            if (in0 > bestm * un0) {
                const float q = in0 / un0;            // exact rounded quotient
                if (q > best) { best = q; bidx = g0; bestm = best * 0.99999952f; }
            }
            if (in1 > bestm * un1) {                  // bestm possibly updated
                const float q = in1 / un1;
                if (q > best) { best = q; bidx = g1; bestm = best * 0.99999952f; }
            }
        }
    }

    // ---- 4-lane argmax reduction (first-occurrence ties -> smaller g) ----
    #pragma unroll
    for (int off = 1; off < LANES; off <<= 1) {
        const float ob = __shfl_xor_sync(0xffffffffu, best, off);
        const int   oi = __shfl_xor_sync(0xffffffffu, bidx, off);
        if (ob > best || (ob == best && oi < bidx)) { best = ob; bidx = oi; }
    }

    // ---- matched_gt (branch-free selects; all lanes compute) ----
    const bool low     = (best <= 0.3f);
    const bool neutral = !low && (best < 0.6f);
    const float4 mb = s_box[bidx];
    const float  mc = s_cls[bidx];
    const float m0 = low ? -1.0f : (neutral ? -NEGBIG : mb.x);
    const float m1 = low ? -1.0f : (neutral ? -NEGBIG : mb.y);
    const float m2 = low ? -1.0f : (neutral ? -NEGBIG : mb.z);
    const float m3 = low ? -1.0f : (neutral ? -NEGBIG : mb.w);
    const float m4 = low ? -1.0f : (neutral ? -NEGBIG : mc);

    if (valid) {
        float* om = out + (size_t)NA * 4 + (size_t)a * 5;
        // select-chain store instead of a 5-branch cascade
        const float mv = (sub == 0) ? m0 : (sub == 1) ? m1 : (sub == 2) ? m2 : m3;
        om[sub] = mv;
        if (sub == 0) om[4] = m4;
    }

    // ---- gt_deltas (lanes 1,2 store halves; expensive path skipped when
    //      unmatched, which is the common case) ----
    if (valid && (sub == 1 || sub == 2)) {
        float gd0, gd1, gd2, gd3;
        if (m0 < 0.0f) {
            gd0 = gd1 = gd2 = gd3 = -NEGBIG;
        } else {
            const float wg = fmaxf(m2 - m0, 1.0f);
            const float hg = fmaxf(m3 - m1, 1.0f);
            const float xg = m0 + wg * 0.5f;
            const float yg = m1 + hg * 0.5f;
            gd0 = (xg - xa) / wa;
            gd1 = (yg - ya) / ha;
            gd2 = logf(wg / wa);
            gd3 = logf(hg / ha);
        }
        // gt_deltas section starts at element NA*9 = 341010 -> byte offset
        // ≡ 8 (mod 16): only 8B-aligned, so float2 stores.
        float* og = out + (size_t)NA * 9 + (size_t)a * 4;
        if (sub == 1) reinterpret_cast<float2*>(og)[0] = make_float2(gd0, gd1);
        else          reinterpret_cast<float2*>(og)[1] = make_float2(gd2, gd3);
    }
}

extern "C" void kernel_launch(void* const* d_in, const int* in_sizes, int n_in,
                              void* d_out, int out_size)
{
    const float* loc3   = (const float*)d_in[0];
    const float* loc4   = (const float*)d_in[1];
    const float* loc5   = (const float*)d_in[2];
    const float* deltas = (const float*)d_in[3];
    const float* gt     = (const float*)d_in[4];
    float* out = (float*)d_out;

    const int threads = 256;
    const int blocks  = (NA * LANES + threads - 1) / threads;  // 593
    rpn_fused_kernel<<<blocks, threads>>>(loc3, loc4, loc5, deltas, gt, out);
}

// round 14
// speedup vs baseline: 1.2610x; 1.1176x over previous
#include <cuda_runtime.h>

#define N3 9604
#define N4 2401
#define N5 625
#define NA 37890            // (N3+N4+N5)*3
#define NGT 64
#define LANES 4             // threads cooperating per anchor
#define SCALE_CLAMP 3.3322045101752038f   // log(224/8), double-rounded
#define NEGBIG 1.0e8f

// Anchor (w,h) per [level*3 + aspect_ratio_index], computed in double on host:
// area = (4*stride)^2; w = sqrt(area/ar); h = area/w;  ar in {0.5, 1.0, 2.0}
__constant__ float c_w[9] = {
    45.254833995939045f,  32.0f,  22.627416997969522f,   // p3 (stride 8)
    90.50966799187809f,   64.0f,  45.254833995939045f,   // p4 (stride 16)
    181.01933598375618f, 128.0f,  90.50966799187809f     // p5 (stride 32)
};
__constant__ float c_h[9] = {
    22.627416997969522f,  32.0f,  45.254833995939045f,
    45.254833995939045f,  64.0f,  90.50966799187809f,
    90.50966799187809f,  128.0f, 181.01933598375618f
};

__global__ __launch_bounds__(256)
void rpn_fused_kernel(const float* __restrict__ loc3,
                      const float* __restrict__ loc4,
                      const float* __restrict__ loc5,
                      const float* __restrict__ deltas,
                      const float* __restrict__ gt,
                      float* __restrict__ out)
{
    __shared__ float4 s_box[NGT];   // gt box coords
    __shared__ float  s_area[NGT];  // gt areas
    __shared__ float  s_cls[NGT];   // gt class

    const int tid = threadIdx.x;
    if (tid < NGT) {
        const float g0 = gt[tid * 5 + 0];
        const float g1 = gt[tid * 5 + 1];
        const float g2 = gt[tid * 5 + 2];
        const float g3 = gt[tid * 5 + 3];
        s_box[tid]  = make_float4(g0, g1, g2, g3);
        s_cls[tid]  = gt[tid * 5 + 4];
        s_area[tid] = (g2 - g0) * (g3 - g1);
    }
    __syncthreads();

    const int gid   = blockIdx.x * blockDim.x + tid;
    const int a_raw = gid >> 2;          // anchor id
    const int sub   = gid & 3;           // lane within group of 4
    const bool valid = (a_raw < NA);
    const int a = valid ? a_raw : 0;     // clamp: no thread exits before shfl

    // ---- which level / location / aspect ratio ----
    int li, r = a;
    const float* loc;
    if (a < 3 * N3)             { li = 0; loc = loc3; }
    else if (a < 3 * (N3 + N4)) { li = 1; loc = loc4; r = a - 3 * N3; }
    else                        { li = 2; loc = loc5; r = a - 3 * (N3 + N4); }
    const int locidx = r / 3;
    const int ar     = r - locidx * 3;

    const float xc = __ldg(&loc[2 * locidx + 0]);
    const float yc = __ldg(&loc[2 * locidx + 1]);
    const float w  = c_w[li * 3 + ar];
    const float h  = c_h[li * 3 + ar];

    // anchor box (matches reference rounding: xc - w/2 etc., all f32)
    const float ax0 = xc - 0.5f * w;
    const float ay0 = yc - 0.5f * h;
    const float ax1 = xc + 0.5f * w;
    const float ay1 = yc + 0.5f * h;

    // recompute wa/ha from the box like the reference does (f32 rounding parity)
    const float wa = ax1 - ax0;
    const float ha = ay1 - ay0;
    const float xa = ax0 + wa * 0.5f;
    const float ya = ay0 + ha * 0.5f;

    // ---- lane 0: apply deltas -> proposals (independent; overlaps IoU loop) ----
    if (sub == 0 && valid) {
        const float4 d  = reinterpret_cast<const float4*>(deltas)[a];
        const float dw  = fminf(d.z, SCALE_CLAMP);
        const float dh  = fminf(d.w, SCALE_CLAMP);
        const float xp  = d.x * wa + xa;
        const float yp  = d.y * ha + ya;
        const float wp  = expf(dw) * wa;
        const float hp  = expf(dh) * ha;
        float4 prop;
        prop.x = xp - 0.5f * wp;
        prop.y = yp - 0.5f * hp;
        prop.z = xp + 0.5f * wp;
        prop.w = yp + 0.5f * hp;
        reinterpret_cast<float4*>(out)[a] = prop;  // out base 16B-aligned
    }

    // ---- IoU argmax over this lane's strided subset (g ≡ sub mod 4),
    // BRANCHLESS via cross-multiplication; ONE exact division after the loop.
    //
    // Candidate beats best iff in_c/un_c > bin/bun ⟺ in_c·bun > bin·un_c
    // (all quantities ≥ 0, un > 0; products ≤ ~3e9, safely inside f32 range).
    // Zero-intersection candidates can never update (0 > bin·un is false),
    // so the all-zero row resolves to (bidx=0, quality 0) == jnp.argmax.
    // Processing in increasing g with strict > preserves first-occurrence
    // ties. The final quality is RN(bin/bun) — the reference's exact rounded
    // quotient for the winning pair — so threshold logic is bit-identical. ----
    const float aarea = wa * ha;
    float bin  = 0.0f;   // intersection of current best
    float bun  = 1.0f;   // union of current best (q = 0/1 = 0 initially)
    int   bidx = 0;
    #pragma unroll
    for (int i = 0; i < 8; ++i) {
        const int g0 = sub + (i << 3);       // sub, sub+8, ... increasing
        const int g1 = g0 + 4;               // interleaved, still increasing
        const float4 b0 = s_box[g0];
        const float4 b1 = s_box[g1];
        const float a0 = s_area[g0];
        const float a1 = s_area[g1];

        float iw0 = fmaxf(fminf(ax1, b0.z) - fmaxf(ax0, b0.x), 0.0f);
        float ih0 = fmaxf(fminf(ay1, b0.w) - fmaxf(ay0, b0.y), 0.0f);
        float iw1 = fmaxf(fminf(ax1, b1.z) - fmaxf(ax0, b1.x), 0.0f);
        float ih1 = fmaxf(fminf(ay1, b1.w) - fmaxf(ay0, b1.y), 0.0f);
        const float in0 = iw0 * ih0;
        const float in1 = iw1 * ih1;
        const float un0 = aarea + a0 - in0;
        const float un1 = aarea + a1 - in1;

        const bool u0 = (in0 * bun) > (bin * un0);
        bin  = u0 ? in0 : bin;
        bun  = u0 ? un0 : bun;
        bidx = u0 ? g0  : bidx;

        const bool u1 = (in1 * bun) > (bin * un1);
        bin  = u1 ? in1 : bin;
        bun  = u1 ? un1 : bun;
        bidx = u1 ? g1  : bidx;
    }

    // ---- 4-lane argmax reduction (cross-mult compare; ties -> smaller g) ----
    #pragma unroll
    for (int off = 1; off < LANES; off <<= 1) {
        const float o_in = __shfl_xor_sync(0xffffffffu, bin,  off);
        const float o_un = __shfl_xor_sync(0xffffffffu, bun,  off);
        const int   o_ix = __shfl_xor_sync(0xffffffffu, bidx, off);
        const float c = o_in * bun;
        const float d = bin  * o_un;
        const bool take = (c > d) || ((c == d) && (o_ix < bidx));
        bin  = take ? o_in : bin;
        bun  = take ? o_un : bun;
        bidx = take ? o_ix : bidx;
    }

    // ---- single exact division: the reference's rounded quality ----
    const float best = bin / bun;

    // ---- matched_gt (branch-free selects; all lanes compute) ----
    const bool low     = (best <= 0.3f);
    const bool neutral = !low && (best < 0.6f);
    const float4 mb = s_box[bidx];
    const float  mc = s_cls[bidx];
    const float m0 = low ? -1.0f : (neutral ? -NEGBIG : mb.x);
    const float m1 = low ? -1.0f : (neutral ? -NEGBIG : mb.y);
    const float m2 = low ? -1.0f : (neutral ? -NEGBIG : mb.z);
    const float m3 = low ? -1.0f : (neutral ? -NEGBIG : mb.w);
    const float m4 = low ? -1.0f : (neutral ? -NEGBIG : mc);

    if (valid) {
        float* om = out + (size_t)NA * 4 + (size_t)a * 5;
        const float mv = (sub == 0) ? m0 : (sub == 1) ? m1 : (sub == 2) ? m2 : m3;
        om[sub] = mv;
        if (sub == 0) om[4] = m4;
    }

    // ---- gt_deltas (lanes 1,2 store halves) ----
    if (valid && (sub == 1 || sub == 2)) {
        float gd0, gd1, gd2, gd3;
        if (m0 < 0.0f) {
            gd0 = gd1 = gd2 = gd3 = -NEGBIG;
        } else {
            const float wg = fmaxf(m2 - m0, 1.0f);
            const float hg = fmaxf(m3 - m1, 1.0f);
            const float xg = m0 + wg * 0.5f;
            const float yg = m1 + hg * 0.5f;
            gd0 = (xg - xa) / wa;
            gd1 = (yg - ya) / ha;
            gd2 = logf(wg / wa);
            gd3 = logf(hg / ha);
        }
        // gt_deltas section starts at element NA*9 = 341010 -> byte offset
        // ≡ 8 (mod 16): only 8B-aligned, so float2 stores.
        float* og = out + (size_t)NA * 9 + (size_t)a * 4;
        if (sub == 1) reinterpret_cast<float2*>(og)[0] = make_float2(gd0, gd1);
        else          reinterpret_cast<float2*>(og)[1] = make_float2(gd2, gd3);
    }
}

extern "C" void kernel_launch(void* const* d_in, const int* in_sizes, int n_in,
                              void* d_out, int out_size)
{
    const float* loc3   = (const float*)d_in[0];
    const float* loc4   = (const float*)d_in[1];
    const float* loc5   = (const float*)d_in[2];
    const float* deltas = (const float*)d_in[3];
    const float* gt     = (const float*)d_in[4];
    float* out = (float*)d_out;

    const int threads = 256;
    const int blocks  = (NA * LANES + threads - 1) / threads;  // 593
    rpn_fused_kernel<<<blocks, threads>>>(loc3, loc4, loc5, deltas, gt, out);
}